// round 13
// baseline (speedup 1.0000x reference)
#include <cuda_runtime.h>

typedef unsigned long long ull;
#define DEVFN __device__ __forceinline__

#define TT 32
#define BB 2048
#define DD 64
#define MT 16
#define NTH 512
#define NCTA (BB / MT)
#define PITCH 20

// smem layout (float offsets)
#define OFF_W0T 0                       // [64][256]  W0T[d][w] = W0[w][d]
#define OFF_W2T (OFF_W0T + 64*256)      // [256][64]  W2T[u][d] = W2[d][u]
#define OFF_B0  (OFF_W2T + 256*64)
#define OFF_B1  (OFF_B0 + 256)
#define OFF_B2  (OFF_B1 + 256)
#define OFF_TS  (OFF_B2 + 64)
#define OFF_Y   (OFF_TS + 32)           // [64][PITCH]
#define OFF_YT  (OFF_Y + 64*PITCH)
#define OFF_K   (OFF_YT + 64*PITCH)     // 6 x [64][PITCH]
#define OFF_H0  (OFF_K + 6*64*PITCH)    // [256][PITCH]
#define OFF_H1  (OFF_H0 + 256*PITCH)    // [256][PITCH]
#define OFF_SCR (OFF_H1 + 256*PITCH)    // 4096 floats reduction scratch
#define SMEM_FLOATS (OFF_SCR + 4096)    // 57952
#define SMEM_BYTES (SMEM_FLOATS * 4)    // 231808 (<= 232448)

__device__ float g_W1D[(256 + 16) * 512];   // [k][2w], value duplicated per pair

__constant__ float c_A[30] = {
    0.f, 0.f, 0.f, 0.f, 0.f,
    0.2f, 0.f, 0.f, 0.f, 0.f,
    (float)(3.0/40.0), (float)(9.0/40.0), 0.f, 0.f, 0.f,
    (float)(44.0/45.0), (float)(-56.0/15.0), (float)(32.0/9.0), 0.f, 0.f,
    (float)(19372.0/6561.0), (float)(-25360.0/2187.0), (float)(64448.0/6561.0), (float)(-212.0/729.0), 0.f,
    (float)(9017.0/3168.0), (float)(-355.0/33.0), (float)(46732.0/5247.0), (float)(49.0/176.0), (float)(-5103.0/18656.0)
};
__constant__ float c_C6[6] = {0.f, 0.2f, 0.3f, 0.8f, (float)(8.0/9.0), 1.f};
__constant__ float c_B6[6] = {(float)(35.0/384.0), 0.f, (float)(500.0/1113.0),
                              (float)(125.0/192.0), (float)(-2187.0/6784.0), (float)(11.0/84.0)};

DEVFN ull dup2(float x) {
    ull r; unsigned xi = __float_as_uint(x);
    asm("mov.b64 %0, {%1, %1};" : "=l"(r) : "r"(xi));
    return r;
}
DEVFN void fma2(ull& d, ull a, ull b) {
    asm("fma.rn.f32x2 %0, %1, %2, %0;" : "+l"(d) : "l"(a), "l"(b));
}
DEVFN ull addx2(ull a, ull b) {
    ull r;
    asm("add.rn.f32x2 %0, %1, %2;" : "=l"(r) : "l"(a), "l"(b));
    return r;
}
DEVFN void unpk(ull v, float& lo, float& hi) {
    unsigned a, b;
    asm("mov.b64 {%0, %1}, %2;" : "=r"(a), "=r"(b) : "l"(v));
    lo = __uint_as_float(a); hi = __uint_as_float(b);
}
DEVFN float fast_tanh(float x) {
    float ax = fabsf(x);
    float e  = __expf(-2.0f * ax);
    float r  = __fdividef(1.0f - e, 1.0f + e);
    return copysignf(r, x);
}

// 4 fma2 on one column (acc[0..3] = row-pairs 0..3) with dup'd B
DEVFN void col4(ull* acc, ull bb, const ulonglong2& a01, const ulonglong2& a23) {
    fma2(acc[0], a01.x, bb); fma2(acc[1], a01.y, bb);
    fma2(acc[2], a23.x, bb); fma2(acc[3], a23.y, bb);
}

DEVFN void scr_store8(float* st, const ull* a) {
    ulonglong2 w0, w1;
    w0.x = a[0]; w0.y = a[1]; w1.x = a[2]; w1.y = a[3];
    *reinterpret_cast<ulonglong2*>(st)     = w0;
    *reinterpret_cast<ulonglong2*>(st + 4) = w1;
}
DEVFN void scr_load_add8(const float* st, ull* a) {
    ulonglong2 q0 = *reinterpret_cast<const ulonglong2*>(st);
    ulonglong2 q1 = *reinterpret_cast<const ulonglong2*>(st + 4);
    a[0] = addx2(a[0], q0.x); a[1] = addx2(a[1], q0.y);
    a[2] = addx2(a[2], q1.x); a[3] = addx2(a[3], q1.y);
}

// kout = (tanh(tanh(aIn@W0T + b0)@W1T + b1)@W2T + b2) * exp(tstage)
DEVFN void vf_eval(float* sm, float tstage, const float* aIn, float* kout, int tid) {
    float et = expf(tstage);
    float* scr = sm + OFF_SCR;

    // ---- GEMM0: k-parity kh=tid>>8 (warp-uniform); col-pair cp x row-half rh ----
    {
        int kh = tid >> 8, t = tid & 255;
        int cp = t & 127, rh = t >> 7;
        int c0 = 2 * cp, rb = 8 * rh;
        ull acc[2][4];
#pragma unroll
        for (int i = 0; i < 2; ++i)
#pragma unroll
            for (int p = 0; p < 4; ++p) acc[i][p] = 0ull;
        const float* pa = aIn + rb;
        const float* pb = sm + OFF_W0T + c0;
#pragma unroll 4
        for (int j = 0; j < 32; ++j) {
            int k = 2 * j + kh;
            float2 b2 = *reinterpret_cast<const float2*>(pb + k * 256);
            ulonglong2 a01 = *reinterpret_cast<const ulonglong2*>(pa + k * PITCH);
            ulonglong2 a23 = *reinterpret_cast<const ulonglong2*>(pa + k * PITCH + 4);
            col4(acc[0], dup2(b2.x), a01, a23);
            col4(acc[1], dup2(b2.y), a01, a23);
        }
        float* st = scr + t * 16;
        if (kh) { scr_store8(st, acc[0]); scr_store8(st + 8, acc[1]); }
        __syncthreads();
        if (!kh) {
            scr_load_add8(st, acc[0]); scr_load_add8(st + 8, acc[1]);
#pragma unroll
            for (int ci = 0; ci < 2; ++ci) {
                float bj = sm[OFF_B0 + c0 + ci];
                float v[8];
#pragma unroll
                for (int p = 0; p < 4; ++p) unpk(acc[ci][p], v[2 * p], v[2 * p + 1]);
#pragma unroll
                for (int i = 0; i < 8; ++i) v[i] = fast_tanh(v[i] + bj);
                float* hp = sm + OFF_H0 + (c0 + ci) * PITCH + rb;
                *reinterpret_cast<float4*>(hp)     = make_float4(v[0], v[1], v[2], v[3]);
                *reinterpret_cast<float4*>(hp + 4) = make_float4(v[4], v[5], v[6], v[7]);
            }
        }
    }
    __syncthreads();

    // ---- GEMM1: k-parity kh=tid>>8; col-quad cg x row-quarter rq; B dup'd via LDG.128 ----
    {
        int kh = tid >> 8, t = tid & 255;
        int cg = t >> 2, rq = t & 3;
        int c0 = 4 * cg, rb = 4 * rq;
        ull acc[4][2];
#pragma unroll
        for (int i = 0; i < 4; ++i) { acc[i][0] = 0ull; acc[i][1] = 0ull; }
        const float* pa = sm + OFF_H0 + rb;
        const float* pb = g_W1D + kh * 512 + 2 * c0;   // k = 2j + kh -> + j*1024
        ulonglong2 bbuf0[4], bbuf1[4];
#pragma unroll
        for (int jj = 0; jj < 4; ++jj) {
            bbuf0[jj] = *reinterpret_cast<const ulonglong2*>(pb + jj * 1024);
            bbuf1[jj] = *reinterpret_cast<const ulonglong2*>(pb + jj * 1024 + 4);
        }
#pragma unroll 4
        for (int j = 0; j < 128; ++j) {
            ulonglong2 b01 = bbuf0[j & 3];   // dup'd cols c0, c0+1
            ulonglong2 b23 = bbuf1[j & 3];   // dup'd cols c0+2, c0+3
            bbuf0[j & 3] = *reinterpret_cast<const ulonglong2*>(pb + (j + 4) * 1024);
            bbuf1[j & 3] = *reinterpret_cast<const ulonglong2*>(pb + (j + 4) * 1024 + 4);
            int k = 2 * j + kh;
            ulonglong2 a01 = *reinterpret_cast<const ulonglong2*>(pa + k * PITCH);  // rows rb..rb+3
            fma2(acc[0][0], a01.x, b01.x); fma2(acc[0][1], a01.y, b01.x);
            fma2(acc[1][0], a01.x, b01.y); fma2(acc[1][1], a01.y, b01.y);
            fma2(acc[2][0], a01.x, b23.x); fma2(acc[2][1], a01.y, b23.x);
            fma2(acc[3][0], a01.x, b23.y); fma2(acc[3][1], a01.y, b23.y);
        }
        float* st = scr + t * 16;
        if (kh) {
            ulonglong2 w0, w1;
            w0.x = acc[0][0]; w0.y = acc[0][1]; w1.x = acc[1][0]; w1.y = acc[1][1];
            *reinterpret_cast<ulonglong2*>(st)     = w0;
            *reinterpret_cast<ulonglong2*>(st + 4) = w1;
            w0.x = acc[2][0]; w0.y = acc[2][1]; w1.x = acc[3][0]; w1.y = acc[3][1];
            *reinterpret_cast<ulonglong2*>(st + 8)  = w0;
            *reinterpret_cast<ulonglong2*>(st + 12) = w1;
        }
        __syncthreads();
        if (!kh) {
            ulonglong2 q0 = *reinterpret_cast<const ulonglong2*>(st);
            ulonglong2 q1 = *reinterpret_cast<const ulonglong2*>(st + 4);
            ulonglong2 q2 = *reinterpret_cast<const ulonglong2*>(st + 8);
            ulonglong2 q3 = *reinterpret_cast<const ulonglong2*>(st + 12);
            acc[0][0] = addx2(acc[0][0], q0.x); acc[0][1] = addx2(acc[0][1], q0.y);
            acc[1][0] = addx2(acc[1][0], q1.x); acc[1][1] = addx2(acc[1][1], q1.y);
            acc[2][0] = addx2(acc[2][0], q2.x); acc[2][1] = addx2(acc[2][1], q2.y);
            acc[3][0] = addx2(acc[3][0], q3.x); acc[3][1] = addx2(acc[3][1], q3.y);
#pragma unroll
            for (int ci = 0; ci < 4; ++ci) {
                float bj = sm[OFF_B1 + c0 + ci];
                float v[4];
                unpk(acc[ci][0], v[0], v[1]);
                unpk(acc[ci][1], v[2], v[3]);
#pragma unroll
                for (int i = 0; i < 4; ++i) v[i] = fast_tanh(v[i] + bj);
                float* hp = sm + OFF_H1 + (c0 + ci) * PITCH + rb;
                *reinterpret_cast<float4*>(hp) = make_float4(v[0], v[1], v[2], v[3]);
            }
        }
    }
    __syncthreads();

    // ---- GEMM2: u-mod-4 us=tid>>7 (warp-uniform); col d x row-half rh ----
    {
        int us = tid >> 7, t = tid & 127;
        int rh = t >> 6, d = t & 63;
        int rb = 8 * rh;
        ull acc2[4];
#pragma unroll
        for (int p = 0; p < 4; ++p) acc2[p] = 0ull;
        const float* pa = sm + OFF_H1 + rb;
        const float* pb = sm + OFF_W2T + d;
#pragma unroll 4
        for (int j = 0; j < 64; ++j) {
            int u = 4 * j + us;
            ull bb = dup2(pb[u * 64]);
            ulonglong2 a01 = *reinterpret_cast<const ulonglong2*>(pa + u * PITCH);
            ulonglong2 a23 = *reinterpret_cast<const ulonglong2*>(pa + u * PITCH + 4);
            col4(acc2, bb, a01, a23);
        }
        if (us) {
            float* st = scr + ((us - 1) * 128 + t) * 8;
            scr_store8(st, acc2);
        }
        __syncthreads();
        if (us == 0) {
#pragma unroll
            for (int p = 0; p < 3; ++p)
                scr_load_add8(scr + (p * 128 + t) * 8, acc2);
            float bd = sm[OFF_B2 + d];
            float v[8];
#pragma unroll
            for (int p = 0; p < 4; ++p) unpk(acc2[p], v[2 * p], v[2 * p + 1]);
#pragma unroll
            for (int i = 0; i < 8; ++i) v[i] = (v[i] + bd) * et;
            float* kd = kout + d * PITCH + rb;
            *reinterpret_cast<float4*>(kd)     = make_float4(v[0], v[1], v[2], v[3]);
            *reinterpret_cast<float4*>(kd + 4) = make_float4(v[4], v[5], v[6], v[7]);
        }
    }
    __syncthreads();
}

__global__ void __launch_bounds__(256, 1)
prep_kernel(const float* __restrict__ W1, const float* __restrict__ y0,
            float* __restrict__ out) {
    int stride = gridDim.x * blockDim.x;
    int t0 = blockIdx.x * blockDim.x + threadIdx.x;
    for (int idx = t0; idx < 256 * 256; idx += stride) {
        int w = idx >> 8, k = idx & 255;
        float v = W1[idx];                     // W1[w][k]
        g_W1D[k * 512 + 2 * w]     = v;        // duplicated pair
        g_W1D[k * 512 + 2 * w + 1] = v;
    }
    for (int idx = t0; idx < 16 * 512; idx += stride)
        g_W1D[131072 + idx] = 0.f;             // prefetch-overrun pad
    for (int idx = t0; idx < BB * DD; idx += stride)
        out[idx] = y0[idx];                    // out slice 0 = y0
}

__global__ void __launch_bounds__(NTH, 1)
ode_kernel(const float* __restrict__ ts, const float* __restrict__ y0,
           const float* __restrict__ W0, const float* __restrict__ b0,
           const float* __restrict__ b1,
           const float* __restrict__ W2, const float* __restrict__ b2,
           float* __restrict__ out) {
    extern __shared__ float sm[];
    int tid = threadIdx.x;
    int r0 = blockIdx.x * MT;

    for (int idx = tid; idx < 64 * 256; idx += NTH) {
        int w = idx >> 6, d = idx & 63;
        sm[OFF_W0T + d * 256 + w] = W0[idx];   // W0T[d][w]
    }
    for (int idx = tid; idx < 64 * 256; idx += NTH) {
        int d = idx >> 8, u = idx & 255;
        sm[OFF_W2T + u * 64 + d] = W2[idx];    // W2T[u][d]
    }
    if (tid < 256) { sm[OFF_B0 + tid] = b0[tid]; sm[OFF_B1 + tid] = b1[tid]; }
    if (tid < 64)  sm[OFF_B2 + tid] = b2[tid];
    if (tid < 32)  sm[OFF_TS + tid] = ts[tid];
    for (int i = tid; i < MT * DD; i += NTH) {
        int d = i >> 4, m = i & 15;
        sm[OFF_Y + d * PITCH + m] = y0[(r0 + m) * DD + d];
    }
    __syncthreads();

    float* sY  = sm + OFF_Y;
    float* sYt = sm + OFF_YT;
    float* sK  = sm + OFF_K;

    for (int iv = 0; iv < TT - 1; ++iv) {
        float t0v = sm[OFF_TS + iv];
        float h   = 0.5f * (sm[OFF_TS + iv + 1] - t0v);
        for (int sub = 0; sub < 2; ++sub) {
            float tc = t0v + sub * h;
            for (int s = 0; s < 6; ++s) {
                const float* aIn = (s == 0) ? sY : sYt;
                vf_eval(sm, tc + h * c_C6[s], aIn, sK + s * 64 * PITCH, tid);
                if (s < 5) {
                    for (int i = tid; i < MT * DD; i += NTH) {
                        int d = i >> 4, m = i & 15;
                        int off = d * PITCH + m;
                        float acc = sY[off];
                        for (int j = 0; j <= s; ++j)
                            acc += h * c_A[(s + 1) * 5 + j] * sK[j * 64 * PITCH + off];
                        sYt[off] = acc;
                    }
                    __syncthreads();
                }
            }
            for (int i = tid; i < MT * DD; i += NTH) {
                int d = i >> 4, m = i & 15;
                int off = d * PITCH + m;
                float acc = sY[off];
                acc += h * (c_B6[0] * sK[0 * 64 * PITCH + off]
                          + c_B6[2] * sK[2 * 64 * PITCH + off]
                          + c_B6[3] * sK[3 * 64 * PITCH + off]
                          + c_B6[4] * sK[4 * 64 * PITCH + off]
                          + c_B6[5] * sK[5 * 64 * PITCH + off]);
                sY[off] = acc;
            }
            __syncthreads();
        }
        float* dst = out + (size_t)(iv + 1) * BB * DD + (size_t)r0 * DD;
        for (int i = tid; i < MT * DD; i += NTH) {
            int m = i >> 6, d = i & 63;
            dst[i] = sY[d * PITCH + m];
        }
    }
}

extern "C" void kernel_launch(void* const* d_in, const int* in_sizes, int n_in,
                              void* d_out, int out_size) {
    if (n_in < 8) return;
    const float* ts = (const float*)d_in[0];
    const float* y0 = (const float*)d_in[1];
    const float* W0 = (const float*)d_in[2];
    const float* b0 = (const float*)d_in[3];
    const float* W1 = (const float*)d_in[4];
    const float* b1 = (const float*)d_in[5];
    const float* W2 = (const float*)d_in[6];
    const float* b2 = (const float*)d_in[7];
    float* out = (float*)d_out;

    cudaFuncSetAttribute(ode_kernel, cudaFuncAttributeMaxDynamicSharedMemorySize, SMEM_BYTES);

    prep_kernel<<<256, 256>>>(W1, y0, out);
    ode_kernel<<<NCTA, NTH, SMEM_BYTES>>>(ts, y0, W0, b0, b1, W2, b2, out);
}

// round 14
// speedup vs baseline: 1.3087x; 1.3087x over previous
#include <cuda_runtime.h>

typedef unsigned long long ull;
#define DEVFN __device__ __forceinline__

#define TT 32
#define BB 2048
#define DD 64
#define MT 16
#define NTH 512
#define NCTA (BB / MT)
#define PITCH 20

// smem layout (float offsets)
#define OFF_W0T 0                       // [64][256]  W0T[d][w] = W0[w][d]
#define OFF_W2T (OFF_W0T + 64*256)      // [256][64]  W2T[u][d] = W2[d][u]
#define OFF_B0  (OFF_W2T + 256*64)
#define OFF_B1  (OFF_B0 + 256)
#define OFF_B2  (OFF_B1 + 256)
#define OFF_TS  (OFF_B2 + 64)
#define OFF_Y   (OFF_TS + 32)           // [64][PITCH]
#define OFF_YT  (OFF_Y + 64*PITCH)
#define OFF_K   (OFF_YT + 64*PITCH)     // 6 x [64][PITCH]
#define OFF_H0  (OFF_K + 6*64*PITCH)    // [256][PITCH]
#define OFF_H1  (OFF_H0 + 256*PITCH)    // [256][PITCH]
#define OFF_SCR (OFF_H1 + 256*PITCH)    // 4096 floats reduction scratch
#define SMEM_FLOATS (OFF_SCR + 4096)    // 57952
#define SMEM_BYTES (SMEM_FLOATS * 4)    // 231808 (<= 232448)

__device__ float g_W1T[(256 + 16) * 256];   // [k][w], w contiguous

__constant__ float c_A[30] = {
    0.f, 0.f, 0.f, 0.f, 0.f,
    0.2f, 0.f, 0.f, 0.f, 0.f,
    (float)(3.0/40.0), (float)(9.0/40.0), 0.f, 0.f, 0.f,
    (float)(44.0/45.0), (float)(-56.0/15.0), (float)(32.0/9.0), 0.f, 0.f,
    (float)(19372.0/6561.0), (float)(-25360.0/2187.0), (float)(64448.0/6561.0), (float)(-212.0/729.0), 0.f,
    (float)(9017.0/3168.0), (float)(-355.0/33.0), (float)(46732.0/5247.0), (float)(49.0/176.0), (float)(-5103.0/18656.0)
};
__constant__ float c_C6[6] = {0.f, 0.2f, 0.3f, 0.8f, (float)(8.0/9.0), 1.f};
__constant__ float c_B6[6] = {(float)(35.0/384.0), 0.f, (float)(500.0/1113.0),
                              (float)(125.0/192.0), (float)(-2187.0/6784.0), (float)(11.0/84.0)};

DEVFN ull dup2(float x) {
    ull r; unsigned xi = __float_as_uint(x);
    asm("mov.b64 %0, {%1, %1};" : "=l"(r) : "r"(xi));
    return r;
}
DEVFN void fma2(ull& d, ull a, ull b) {
    asm("fma.rn.f32x2 %0, %1, %2, %0;" : "+l"(d) : "l"(a), "l"(b));
}
DEVFN ull addx2(ull a, ull b) {
    ull r;
    asm("add.rn.f32x2 %0, %1, %2;" : "=l"(r) : "l"(a), "l"(b));
    return r;
}
DEVFN void unpk(ull v, float& lo, float& hi) {
    unsigned a, b;
    asm("mov.b64 {%0, %1}, %2;" : "=r"(a), "=r"(b) : "l"(v));
    lo = __uint_as_float(a); hi = __uint_as_float(b);
}
DEVFN float fast_tanh(float x) {
    float ax = fabsf(x);
    float e  = __expf(-2.0f * ax);
    float r  = __fdividef(1.0f - e, 1.0f + e);
    return copysignf(r, x);
}

// 4 fma2 on one column (acc[0..3] = row-pairs 0..3) with dup'd B
DEVFN void col4(ull* acc, ull bb, const ulonglong2& a01, const ulonglong2& a23) {
    fma2(acc[0], a01.x, bb); fma2(acc[1], a01.y, bb);
    fma2(acc[2], a23.x, bb); fma2(acc[3], a23.y, bb);
}

// kout = (tanh(tanh(aIn@W0T + b0)@W1T + b1)@W2T + b2) * exp(tstage)
DEVFN void vf_eval(float* sm, float tstage, const float* aIn, float* kout, int tid) {
    float et = expf(tstage);
    float* scr = sm + OFF_SCR;

    // ---- GEMM0: k-parity kh=tid>>8 (warp-uniform); col-pair cp x row-half rh ----
    {
        int kh = tid >> 8, t = tid & 255;
        int cp = t & 127, rh = t >> 7;
        int c0 = 2 * cp, rb = 8 * rh;
        ull acc[2][4];
#pragma unroll
        for (int i = 0; i < 2; ++i)
#pragma unroll
            for (int p = 0; p < 4; ++p) acc[i][p] = 0ull;
        const float* pa = aIn + rb;
        const float* pb = sm + OFF_W0T + c0;
#pragma unroll 4
        for (int j = 0; j < 32; ++j) {
            int k = 2 * j + kh;
            float2 b2 = *reinterpret_cast<const float2*>(pb + k * 256);
            ulonglong2 a01 = *reinterpret_cast<const ulonglong2*>(pa + k * PITCH);
            ulonglong2 a23 = *reinterpret_cast<const ulonglong2*>(pa + k * PITCH + 4);
            col4(acc[0], dup2(b2.x), a01, a23);
            col4(acc[1], dup2(b2.y), a01, a23);
        }
        // coalesced scratch: piece c (ulonglong2) at scr + c*1024 + t*4
        if (kh) {
#pragma unroll
            for (int c = 0; c < 4; ++c) {
                ulonglong2 w;
                w.x = acc[c >> 1][2 * (c & 1)];
                w.y = acc[c >> 1][2 * (c & 1) + 1];
                *reinterpret_cast<ulonglong2*>(scr + c * 1024 + t * 4) = w;
            }
        }
        __syncthreads();
        if (!kh) {
#pragma unroll
            for (int c = 0; c < 4; ++c) {
                ulonglong2 q = *reinterpret_cast<const ulonglong2*>(scr + c * 1024 + t * 4);
                acc[c >> 1][2 * (c & 1)]     = addx2(acc[c >> 1][2 * (c & 1)], q.x);
                acc[c >> 1][2 * (c & 1) + 1] = addx2(acc[c >> 1][2 * (c & 1) + 1], q.y);
            }
#pragma unroll
            for (int ci = 0; ci < 2; ++ci) {
                float bj = sm[OFF_B0 + c0 + ci];
                float v[8];
#pragma unroll
                for (int p = 0; p < 4; ++p) unpk(acc[ci][p], v[2 * p], v[2 * p + 1]);
#pragma unroll
                for (int i = 0; i < 8; ++i) v[i] = fast_tanh(v[i] + bj);
                float* hp = sm + OFF_H0 + (c0 + ci) * PITCH + rb;
                *reinterpret_cast<float4*>(hp)     = make_float4(v[0], v[1], v[2], v[3]);
                *reinterpret_cast<float4*>(hp + 4) = make_float4(v[4], v[5], v[6], v[7]);
            }
        }
    }
    __syncthreads();

    // ---- GEMM1: k-parity kh=tid>>8; col-quad cg x row-quarter rq; B plain LDG.128 ----
    {
        int kh = tid >> 8, t = tid & 255;
        int cg = t >> 2, rq = t & 3;
        int c0 = 4 * cg, rb = 4 * rq;
        ull acc[4][2];
#pragma unroll
        for (int i = 0; i < 4; ++i) { acc[i][0] = 0ull; acc[i][1] = 0ull; }
        const float* pa = sm + OFF_H0 + rb;
        const float* pb = g_W1T + kh * 256 + c0;   // k = 2j + kh -> + j*512
        float4 bbuf[4];
#pragma unroll
        for (int jj = 0; jj < 4; ++jj)
            bbuf[jj] = *reinterpret_cast<const float4*>(pb + jj * 512);
#pragma unroll 4
        for (int j = 0; j < 128; ++j) {
            float4 b4 = bbuf[j & 3];
            bbuf[j & 3] = *reinterpret_cast<const float4*>(pb + (j + 4) * 512);
            int k = 2 * j + kh;
            ulonglong2 a01 = *reinterpret_cast<const ulonglong2*>(pa + k * PITCH);  // rows rb..rb+3
            ull d0 = dup2(b4.x), d1 = dup2(b4.y), d2 = dup2(b4.z), d3 = dup2(b4.w);
            fma2(acc[0][0], a01.x, d0); fma2(acc[0][1], a01.y, d0);
            fma2(acc[1][0], a01.x, d1); fma2(acc[1][1], a01.y, d1);
            fma2(acc[2][0], a01.x, d2); fma2(acc[2][1], a01.y, d2);
            fma2(acc[3][0], a01.x, d3); fma2(acc[3][1], a01.y, d3);
        }
        // coalesced scratch: piece ci at scr + ci*1024 + t*4
        if (kh) {
#pragma unroll
            for (int ci = 0; ci < 4; ++ci) {
                ulonglong2 w;
                w.x = acc[ci][0]; w.y = acc[ci][1];
                *reinterpret_cast<ulonglong2*>(scr + ci * 1024 + t * 4) = w;
            }
        }
        __syncthreads();
        if (!kh) {
#pragma unroll
            for (int ci = 0; ci < 4; ++ci) {
                ulonglong2 q = *reinterpret_cast<const ulonglong2*>(scr + ci * 1024 + t * 4);
                acc[ci][0] = addx2(acc[ci][0], q.x);
                acc[ci][1] = addx2(acc[ci][1], q.y);
                float bj = sm[OFF_B1 + c0 + ci];
                float v[4];
                unpk(acc[ci][0], v[0], v[1]);
                unpk(acc[ci][1], v[2], v[3]);
#pragma unroll
                for (int i = 0; i < 4; ++i) v[i] = fast_tanh(v[i] + bj);
                float* hp = sm + OFF_H1 + (c0 + ci) * PITCH + rb;
                *reinterpret_cast<float4*>(hp) = make_float4(v[0], v[1], v[2], v[3]);
            }
        }
    }
    __syncthreads();

    // ---- GEMM2: u-mod-4 us=tid>>7 (warp-uniform); col d x row-half rh ----
    {
        int us = tid >> 7, t = tid & 127;
        int rh = t >> 6, d = t & 63;
        int rb = 8 * rh;
        ull acc2[4];
#pragma unroll
        for (int p = 0; p < 4; ++p) acc2[p] = 0ull;
        const float* pa = sm + OFF_H1 + rb;
        const float* pb = sm + OFF_W2T + d;
#pragma unroll 4
        for (int j = 0; j < 64; ++j) {
            int u = 4 * j + us;
            ull bb = dup2(pb[u * 64]);
            ulonglong2 a01 = *reinterpret_cast<const ulonglong2*>(pa + u * PITCH);
            ulonglong2 a23 = *reinterpret_cast<const ulonglong2*>(pa + u * PITCH + 4);
            col4(acc2, bb, a01, a23);
        }
        // coalesced scratch: piece c at scr + (us-1)*1024 + c*512 + t*4
        if (us) {
#pragma unroll
            for (int c = 0; c < 2; ++c) {
                ulonglong2 w;
                w.x = acc2[2 * c]; w.y = acc2[2 * c + 1];
                *reinterpret_cast<ulonglong2*>(scr + (us - 1) * 1024 + c * 512 + t * 4) = w;
            }
        }
        __syncthreads();
        if (us == 0) {
#pragma unroll
            for (int p = 0; p < 3; ++p)
#pragma unroll
                for (int c = 0; c < 2; ++c) {
                    ulonglong2 q = *reinterpret_cast<const ulonglong2*>(scr + p * 1024 + c * 512 + t * 4);
                    acc2[2 * c]     = addx2(acc2[2 * c], q.x);
                    acc2[2 * c + 1] = addx2(acc2[2 * c + 1], q.y);
                }
            float bd = sm[OFF_B2 + d];
            float v[8];
#pragma unroll
            for (int p = 0; p < 4; ++p) unpk(acc2[p], v[2 * p], v[2 * p + 1]);
#pragma unroll
            for (int i = 0; i < 8; ++i) v[i] = (v[i] + bd) * et;
            float* kd = kout + d * PITCH + rb;
            *reinterpret_cast<float4*>(kd)     = make_float4(v[0], v[1], v[2], v[3]);
            *reinterpret_cast<float4*>(kd + 4) = make_float4(v[4], v[5], v[6], v[7]);
        }
    }
    __syncthreads();
}

__global__ void __launch_bounds__(256, 1)
prep_kernel(const float* __restrict__ W1, const float* __restrict__ y0,
            float* __restrict__ out) {
    int stride = gridDim.x * blockDim.x;
    int t0 = blockIdx.x * blockDim.x + threadIdx.x;
    for (int idx = t0; idx < 256 * 256; idx += stride) {
        int r = idx >> 8, c = idx & 255;
        g_W1T[c * 256 + r] = W1[idx];          // g_W1T[k][w] = W1[w][k]
    }
    for (int idx = t0; idx < 16 * 256; idx += stride)
        g_W1T[65536 + idx] = 0.f;              // prefetch-overrun pad
    for (int idx = t0; idx < BB * DD; idx += stride)
        out[idx] = y0[idx];                    // out slice 0 = y0
}

__global__ void __launch_bounds__(NTH, 1)
ode_kernel(const float* __restrict__ ts, const float* __restrict__ y0,
           const float* __restrict__ W0, const float* __restrict__ b0,
           const float* __restrict__ b1,
           const float* __restrict__ W2, const float* __restrict__ b2,
           float* __restrict__ out) {
    extern __shared__ float sm[];
    int tid = threadIdx.x;
    int r0 = blockIdx.x * MT;

    for (int idx = tid; idx < 64 * 256; idx += NTH) {
        int w = idx >> 6, d = idx & 63;
        sm[OFF_W0T + d * 256 + w] = W0[idx];   // W0T[d][w]
    }
    for (int idx = tid; idx < 64 * 256; idx += NTH) {
        int d = idx >> 8, u = idx & 255;
        sm[OFF_W2T + u * 64 + d] = W2[idx];    // W2T[u][d]
    }
    if (tid < 256) { sm[OFF_B0 + tid] = b0[tid]; sm[OFF_B1 + tid] = b1[tid]; }
    if (tid < 64)  sm[OFF_B2 + tid] = b2[tid];
    if (tid < 32)  sm[OFF_TS + tid] = ts[tid];
    for (int i = tid; i < MT * DD; i += NTH) {
        int d = i >> 4, m = i & 15;
        sm[OFF_Y + d * PITCH + m] = y0[(r0 + m) * DD + d];
    }
    __syncthreads();

    float* sY  = sm + OFF_Y;
    float* sYt = sm + OFF_YT;
    float* sK  = sm + OFF_K;

    for (int iv = 0; iv < TT - 1; ++iv) {
        float t0v = sm[OFF_TS + iv];
        float h   = 0.5f * (sm[OFF_TS + iv + 1] - t0v);
        for (int sub = 0; sub < 2; ++sub) {
            float tc = t0v + sub * h;
            for (int s = 0; s < 6; ++s) {
                const float* aIn = (s == 0) ? sY : sYt;
                vf_eval(sm, tc + h * c_C6[s], aIn, sK + s * 64 * PITCH, tid);
                if (s < 5) {
                    for (int i = tid; i < MT * DD; i += NTH) {
                        int d = i >> 4, m = i & 15;
                        int off = d * PITCH + m;
                        float acc = sY[off];
                        for (int j = 0; j <= s; ++j)
                            acc += h * c_A[(s + 1) * 5 + j] * sK[j * 64 * PITCH + off];
                        sYt[off] = acc;
                    }
                    __syncthreads();
                }
            }
            for (int i = tid; i < MT * DD; i += NTH) {
                int d = i >> 4, m = i & 15;
                int off = d * PITCH + m;
                float acc = sY[off];
                acc += h * (c_B6[0] * sK[0 * 64 * PITCH + off]
                          + c_B6[2] * sK[2 * 64 * PITCH + off]
                          + c_B6[3] * sK[3 * 64 * PITCH + off]
                          + c_B6[4] * sK[4 * 64 * PITCH + off]
                          + c_B6[5] * sK[5 * 64 * PITCH + off]);
                sY[off] = acc;
            }
            __syncthreads();
        }
        float* dst = out + (size_t)(iv + 1) * BB * DD + (size_t)r0 * DD;
        for (int i = tid; i < MT * DD; i += NTH) {
            int m = i >> 6, d = i & 63;
            dst[i] = sY[d * PITCH + m];
        }
    }
}

extern "C" void kernel_launch(void* const* d_in, const int* in_sizes, int n_in,
                              void* d_out, int out_size) {
    if (n_in < 8) return;
    const float* ts = (const float*)d_in[0];
    const float* y0 = (const float*)d_in[1];
    const float* W0 = (const float*)d_in[2];
    const float* b0 = (const float*)d_in[3];
    const float* W1 = (const float*)d_in[4];
    const float* b1 = (const float*)d_in[5];
    const float* W2 = (const float*)d_in[6];
    const float* b2 = (const float*)d_in[7];
    float* out = (float*)d_out;

    cudaFuncSetAttribute(ode_kernel, cudaFuncAttributeMaxDynamicSharedMemorySize, SMEM_BYTES);

    prep_kernel<<<256, 256>>>(W1, y0, out);
    ode_kernel<<<NCTA, NTH, SMEM_BYTES>>>(ts, y0, W0, b0, b1, W2, b2, out);
}

// round 15
// speedup vs baseline: 1.6545x; 1.2642x over previous
#include <cuda_runtime.h>

typedef unsigned long long ull;
#define DEVFN __device__ __forceinline__

#define TT 32
#define BB 2048
#define DD 64
#define MT 16
#define NTH 512
#define NCTA (BB / MT)
#define HP 20    // pitch for H/Y arrays (mod-32 spread, 16B-aligned)

// smem layout (float offsets)
#define OFF_W0T 0                        // [64][256]  W0T[d][w] = W0[w][d]
#define OFF_B0  (OFF_W0T + 64*256)       // 16384
#define OFF_B1  (OFF_B0 + 256)
#define OFF_B2  (OFF_B1 + 256)
#define OFF_TS  (OFF_B2 + 64)
#define OFF_Y   (OFF_TS + 32)            // [64][HP]
#define OFF_YT  (OFF_Y + 64*HP)
#define OFF_K   (OFF_YT + 64*HP)         // [5][128][8] per-thread k storage
#define OFF_H0  (OFF_K + 5*128*8)        // [256][HP]
#define OFF_H1  (OFF_H0 + 256*HP)
#define OFF_SCRA (OFF_H1 + 256*HP)       // 4096
#define OFF_SCRB (OFF_SCRA + 4096)       // 4096
#define SMEM_FLOATS (OFF_SCRB + 4096)    // 43104
#define SMEM_BYTES (SMEM_FLOATS * 4)     // 172416

__device__ float g_W1T[(256 + 16) * 256];  // [k][w], w contiguous (+pad)
__device__ float g_W2T[(256 + 16) * 64];   // [u][d], d contiguous (+pad)

__constant__ float c_A[30] = {
    0.f, 0.f, 0.f, 0.f, 0.f,
    0.2f, 0.f, 0.f, 0.f, 0.f,
    (float)(3.0/40.0), (float)(9.0/40.0), 0.f, 0.f, 0.f,
    (float)(44.0/45.0), (float)(-56.0/15.0), (float)(32.0/9.0), 0.f, 0.f,
    (float)(19372.0/6561.0), (float)(-25360.0/2187.0), (float)(64448.0/6561.0), (float)(-212.0/729.0), 0.f,
    (float)(9017.0/3168.0), (float)(-355.0/33.0), (float)(46732.0/5247.0), (float)(49.0/176.0), (float)(-5103.0/18656.0)
};
__constant__ float c_C6[6] = {0.f, 0.2f, 0.3f, 0.8f, (float)(8.0/9.0), 1.f};
__constant__ float c_B6[6] = {(float)(35.0/384.0), 0.f, (float)(500.0/1113.0),
                              (float)(125.0/192.0), (float)(-2187.0/6784.0), (float)(11.0/84.0)};

DEVFN ull dup2(float x) {
    ull r; unsigned xi = __float_as_uint(x);
    asm("mov.b64 %0, {%1, %1};" : "=l"(r) : "r"(xi));
    return r;
}
DEVFN void fma2(ull& d, ull a, ull b) {
    asm("fma.rn.f32x2 %0, %1, %2, %0;" : "+l"(d) : "l"(a), "l"(b));
}
DEVFN ull addx2(ull a, ull b) {
    ull r;
    asm("add.rn.f32x2 %0, %1, %2;" : "=l"(r) : "l"(a), "l"(b));
    return r;
}
DEVFN void unpk(ull v, float& lo, float& hi) {
    unsigned a, b;
    asm("mov.b64 {%0, %1}, %2;" : "=r"(a), "=r"(b) : "l"(v));
    lo = __uint_as_float(a); hi = __uint_as_float(b);
}
DEVFN float fast_tanh(float x) {
    float ax = fabsf(x);
    float e  = __expf(-2.0f * ax);
    float r  = __fdividef(1.0f - e, 1.0f + e);
    return copysignf(r, x);
}

// 4 fma2 on one column (acc[0..3] = row-pairs) with dup'd B
DEVFN void col4(ull* acc, ull bb, const ulonglong2& a01, const ulonglong2& a23) {
    fma2(acc[0], a01.x, bb); fma2(acc[1], a01.y, bb);
    fma2(acc[2], a23.x, bb); fma2(acc[3], a23.y, bb);
}

// one dopri5 stage s: compute k_{s+1} and fold tableau (yt / y update) into the epilogue
DEVFN void vf_eval(float* sm, int s, float h, float tstage, const float* aIn, int tid) {
    float* scrA = sm + OFF_SCRA;
    float* scrB = sm + OFF_SCRB;

    // thread mappings (tid>>7 serves as both GEMM1 k-split and GEMM2 u-split; warp-uniform)
    int grp = tid >> 7;                   // 0..3
    int t1  = tid & 127;
    int cg = t1 >> 1, rh1 = t1 & 1;       // GEMM1: col-quad, row-half
    int c1 = 4 * cg, rb1 = 8 * rh1;
    int rh2 = t1 >> 6, d2 = t1 & 63;      // GEMM2: row-half, col
    int rb2 = 8 * rh2;
    int t4 = t1 * 4;

    // hoisted B prefetches (L2 latency hides behind GEMM0)
    const float* pb1 = g_W1T + grp * 256 + c1;
    float4 bbuf[4];
#pragma unroll
    for (int jj = 0; jj < 4; ++jj)
        bbuf[jj] = *reinterpret_cast<const float4*>(pb1 + jj * 1024);
    const float* pb2 = g_W2T + grp * 64 + d2;
    float bw[4];
#pragma unroll
    for (int jj = 0; jj < 4; ++jj)
        bw[jj] = pb2[jj * 256];

    // ---- GEMM0: k-parity kh=tid>>8; col-pair cp x row-half rh ----
    {
        int kh = tid >> 8, t = tid & 255;
        int cp = t & 127, rh = t >> 7;
        int c0 = 2 * cp, rb = 8 * rh;
        ull acc[8];
#pragma unroll
        for (int p = 0; p < 8; ++p) acc[p] = 0ull;
        const float* pa = aIn + rb;
        const float* pb = sm + OFF_W0T + c0;
#pragma unroll 4
        for (int j = 0; j < 32; ++j) {
            int k = 2 * j + kh;
            float2 b2 = *reinterpret_cast<const float2*>(pb + k * 256);
            ulonglong2 a01 = *reinterpret_cast<const ulonglong2*>(pa + k * HP);
            ulonglong2 a23 = *reinterpret_cast<const ulonglong2*>(pa + k * HP + 4);
            col4(acc,     dup2(b2.x), a01, a23);
            col4(acc + 4, dup2(b2.y), a01, a23);
        }
        int tt4 = t * 4;
        if (kh) {
#pragma unroll
            for (int p = 0; p < 4; ++p) {
                ulonglong2 w; w.x = acc[2 * p]; w.y = acc[2 * p + 1];
                *reinterpret_cast<ulonglong2*>(scrA + p * 1024 + tt4) = w;
            }
        }
        __syncthreads();                                   // S1
        if (!kh) {
#pragma unroll
            for (int p = 0; p < 4; ++p) {
                ulonglong2 q = *reinterpret_cast<const ulonglong2*>(scrA + p * 1024 + tt4);
                acc[2 * p]     = addx2(acc[2 * p], q.x);
                acc[2 * p + 1] = addx2(acc[2 * p + 1], q.y);
            }
#pragma unroll
            for (int ci = 0; ci < 2; ++ci) {
                float bj = sm[OFF_B0 + c0 + ci];
                float v[8];
#pragma unroll
                for (int p = 0; p < 4; ++p) unpk(acc[ci * 4 + p], v[2 * p], v[2 * p + 1]);
#pragma unroll
                for (int i = 0; i < 8; ++i) v[i] = fast_tanh(v[i] + bj);
                float* hp = sm + OFF_H0 + (c0 + ci) * HP + rb;
                *reinterpret_cast<float4*>(hp)     = make_float4(v[0], v[1], v[2], v[3]);
                *reinterpret_cast<float4*>(hp + 4) = make_float4(v[4], v[5], v[6], v[7]);
            }
        }
    }
    __syncthreads();                                       // S2

    // ---- GEMM1: 4-way k-split (grp); col-quad x row-half (R9 tile economy) ----
    {
        ull acc[16];
#pragma unroll
        for (int p = 0; p < 16; ++p) acc[p] = 0ull;
        const float* pa = sm + OFF_H0 + rb1;
#pragma unroll 4
        for (int j = 0; j < 64; ++j) {
            float4 b4 = bbuf[j & 3];
            bbuf[j & 3] = *reinterpret_cast<const float4*>(pb1 + (j + 4) * 1024);
            int k = 4 * j + grp;
            ulonglong2 a01 = *reinterpret_cast<const ulonglong2*>(pa + k * HP);
            ulonglong2 a23 = *reinterpret_cast<const ulonglong2*>(pa + k * HP + 4);
            col4(acc,      dup2(b4.x), a01, a23);
            col4(acc + 4,  dup2(b4.y), a01, a23);
            col4(acc + 8,  dup2(b4.z), a01, a23);
            col4(acc + 12, dup2(b4.w), a01, a23);
        }
        if (grp == 1) {
#pragma unroll
            for (int p = 0; p < 8; ++p) {
                ulonglong2 w; w.x = acc[2 * p]; w.y = acc[2 * p + 1];
                *reinterpret_cast<ulonglong2*>(scrA + p * 512 + t4) = w;
            }
        } else if (grp == 3) {
#pragma unroll
            for (int p = 0; p < 8; ++p) {
                ulonglong2 w; w.x = acc[2 * p]; w.y = acc[2 * p + 1];
                *reinterpret_cast<ulonglong2*>(scrB + p * 512 + t4) = w;
            }
        }
        __syncthreads();                                   // S3
        if (grp == 0) {
#pragma unroll
            for (int p = 0; p < 8; ++p) {
                ulonglong2 q = *reinterpret_cast<const ulonglong2*>(scrA + p * 512 + t4);
                acc[2 * p]     = addx2(acc[2 * p], q.x);
                acc[2 * p + 1] = addx2(acc[2 * p + 1], q.y);
            }
        } else if (grp == 2) {
#pragma unroll
            for (int p = 0; p < 8; ++p) {
                ulonglong2 q = *reinterpret_cast<const ulonglong2*>(scrB + p * 512 + t4);
                acc[2 * p]     = addx2(acc[2 * p], q.x);
                acc[2 * p + 1] = addx2(acc[2 * p + 1], q.y);
            }
#pragma unroll
            for (int p = 0; p < 8; ++p) {
                ulonglong2 w; w.x = acc[2 * p]; w.y = acc[2 * p + 1];
                *reinterpret_cast<ulonglong2*>(scrB + p * 512 + t4) = w;
            }
        }
        __syncthreads();                                   // S4
        if (grp == 0) {
#pragma unroll
            for (int p = 0; p < 8; ++p) {
                ulonglong2 q = *reinterpret_cast<const ulonglong2*>(scrB + p * 512 + t4);
                acc[2 * p]     = addx2(acc[2 * p], q.x);
                acc[2 * p + 1] = addx2(acc[2 * p + 1], q.y);
            }
#pragma unroll
            for (int ci = 0; ci < 4; ++ci) {
                float bj = sm[OFF_B1 + c1 + ci];
                float v[8];
#pragma unroll
                for (int p = 0; p < 4; ++p) unpk(acc[ci * 4 + p], v[2 * p], v[2 * p + 1]);
#pragma unroll
                for (int i = 0; i < 8; ++i) v[i] = fast_tanh(v[i] + bj);
                float* hp = sm + OFF_H1 + (c1 + ci) * HP + rb1;
                *reinterpret_cast<float4*>(hp)     = make_float4(v[0], v[1], v[2], v[3]);
                *reinterpret_cast<float4*>(hp + 4) = make_float4(v[4], v[5], v[6], v[7]);
            }
        }
    }
    __syncthreads();                                       // S5

    // ---- GEMM2: 4-way u-split (grp); col d x row-half; tableau folded into epilogue ----
    {
        ull acc2[4];
#pragma unroll
        for (int p = 0; p < 4; ++p) acc2[p] = 0ull;
        const float* pa = sm + OFF_H1 + rb2;
#pragma unroll 4
        for (int j = 0; j < 64; ++j) {
            float b = bw[j & 3];
            bw[j & 3] = pb2[(j + 4) * 256];
            int u = 4 * j + grp;
            ull bb = dup2(b);
            ulonglong2 a01 = *reinterpret_cast<const ulonglong2*>(pa + u * HP);
            ulonglong2 a23 = *reinterpret_cast<const ulonglong2*>(pa + u * HP + 4);
            col4(acc2, bb, a01, a23);
        }
        if (grp) {
#pragma unroll
            for (int p = 0; p < 2; ++p) {
                ulonglong2 w; w.x = acc2[2 * p]; w.y = acc2[2 * p + 1];
                *reinterpret_cast<ulonglong2*>(scrA + (grp - 1) * 1024 + p * 512 + t4) = w;
            }
        }
        __syncthreads();                                   // S6
        if (grp == 0) {
#pragma unroll
            for (int pc = 0; pc < 3; ++pc)
#pragma unroll
                for (int p = 0; p < 2; ++p) {
                    ulonglong2 q = *reinterpret_cast<const ulonglong2*>(scrA + pc * 1024 + p * 512 + t4);
                    acc2[2 * p]     = addx2(acc2[2 * p], q.x);
                    acc2[2 * p + 1] = addx2(acc2[2 * p + 1], q.y);
                }
            float et = expf(tstage);
            float bd = sm[OFF_B2 + d2];
            float v[8];
#pragma unroll
            for (int p = 0; p < 4; ++p) unpk(acc2[p], v[2 * p], v[2 * p + 1]);
#pragma unroll
            for (int i = 0; i < 8; ++i) v[i] = (v[i] + bd) * et;   // k_{s+1}[d2][rb2..rb2+7]

            float* kb = sm + OFF_K + t1 * 8;
            const float* yp = sm + OFF_Y + d2 * HP + rb2;
            float4 ya = *reinterpret_cast<const float4*>(yp);
            float4 yb = *reinterpret_cast<const float4*>(yp + 4);
            float yv[8] = {ya.x, ya.y, ya.z, ya.w, yb.x, yb.y, yb.z, yb.w};
            float ac[8];
            if (s < 5) {
                *reinterpret_cast<float4*>(kb + s * 1024)     = make_float4(v[0], v[1], v[2], v[3]);
                *reinterpret_cast<float4*>(kb + s * 1024 + 4) = make_float4(v[4], v[5], v[6], v[7]);
                float alast = c_A[(s + 1) * 5 + s];
#pragma unroll
                for (int i = 0; i < 8; ++i) ac[i] = alast * v[i];
                for (int j = 0; j < s; ++j) {
                    float aj = c_A[(s + 1) * 5 + j];
                    float4 ka = *reinterpret_cast<const float4*>(kb + j * 1024);
                    float4 kc = *reinterpret_cast<const float4*>(kb + j * 1024 + 4);
                    ac[0] += aj * ka.x; ac[1] += aj * ka.y; ac[2] += aj * ka.z; ac[3] += aj * ka.w;
                    ac[4] += aj * kc.x; ac[5] += aj * kc.y; ac[6] += aj * kc.z; ac[7] += aj * kc.w;
                }
                float* ytp = sm + OFF_YT + d2 * HP + rb2;
                *reinterpret_cast<float4*>(ytp)     = make_float4(yv[0] + h * ac[0], yv[1] + h * ac[1],
                                                                  yv[2] + h * ac[2], yv[3] + h * ac[3]);
                *reinterpret_cast<float4*>(ytp + 4) = make_float4(yv[4] + h * ac[4], yv[5] + h * ac[5],
                                                                  yv[6] + h * ac[6], yv[7] + h * ac[7]);
            } else {
#pragma unroll
                for (int i = 0; i < 8; ++i) ac[i] = c_B6[5] * v[i];
#pragma unroll
                for (int jj = 0; jj < 4; ++jj) {
                    const int jlist[4] = {0, 2, 3, 4};
                    int j = jlist[jj];
                    float aj = c_B6[j];
                    float4 ka = *reinterpret_cast<const float4*>(kb + j * 1024);
                    float4 kc = *reinterpret_cast<const float4*>(kb + j * 1024 + 4);
                    ac[0] += aj * ka.x; ac[1] += aj * ka.y; ac[2] += aj * ka.z; ac[3] += aj * ka.w;
                    ac[4] += aj * kc.x; ac[5] += aj * kc.y; ac[6] += aj * kc.z; ac[7] += aj * kc.w;
                }
                float* ypo = sm + OFF_Y + d2 * HP + rb2;
                *reinterpret_cast<float4*>(ypo)     = make_float4(yv[0] + h * ac[0], yv[1] + h * ac[1],
                                                                  yv[2] + h * ac[2], yv[3] + h * ac[3]);
                *reinterpret_cast<float4*>(ypo + 4) = make_float4(yv[4] + h * ac[4], yv[5] + h * ac[5],
                                                                  yv[6] + h * ac[6], yv[7] + h * ac[7]);
            }
        }
    }
    __syncthreads();                                       // S7
}

__global__ void __launch_bounds__(256, 1)
prep_kernel(const float* __restrict__ W1, const float* __restrict__ W2,
            const float* __restrict__ y0, float* __restrict__ out) {
    int stride = gridDim.x * blockDim.x;
    int t0 = blockIdx.x * blockDim.x + threadIdx.x;
    for (int idx = t0; idx < 256 * 256; idx += stride) {
        int r = idx >> 8, c = idx & 255;
        g_W1T[c * 256 + r] = W1[idx];          // g_W1T[k][w] = W1[w][k]
    }
    for (int idx = t0; idx < 16 * 256; idx += stride)
        g_W1T[65536 + idx] = 0.f;              // prefetch-overrun pad
    for (int idx = t0; idx < 64 * 256; idx += stride) {
        int d = idx >> 8, u = idx & 255;
        g_W2T[u * 64 + d] = W2[idx];           // g_W2T[u][d] = W2[d][u]
    }
    for (int idx = t0; idx < 16 * 64; idx += stride)
        g_W2T[16384 + idx] = 0.f;              // prefetch-overrun pad
    for (int idx = t0; idx < BB * DD; idx += stride)
        out[idx] = y0[idx];                    // out slice 0 = y0
}

__global__ void __launch_bounds__(NTH, 1)
ode_kernel(const float* __restrict__ ts, const float* __restrict__ y0,
           const float* __restrict__ W0, const float* __restrict__ b0,
           const float* __restrict__ b1, const float* __restrict__ b2,
           float* __restrict__ out) {
    extern __shared__ float sm[];
    int tid = threadIdx.x;
    int r0 = blockIdx.x * MT;

    for (int idx = tid; idx < 64 * 256; idx += NTH) {
        int w = idx >> 6, d = idx & 63;
        sm[OFF_W0T + d * 256 + w] = W0[idx];   // W0T[d][w]
    }
    if (tid < 256) { sm[OFF_B0 + tid] = b0[tid]; sm[OFF_B1 + tid] = b1[tid]; }
    if (tid < 64)  sm[OFF_B2 + tid] = b2[tid];
    if (tid < 32)  sm[OFF_TS + tid] = ts[tid];
    for (int i = tid; i < MT * DD; i += NTH) {
        int d = i >> 4, m = i & 15;
        sm[OFF_Y + d * HP + m] = y0[(r0 + m) * DD + d];
    }
    __syncthreads();

    float* sY  = sm + OFF_Y;
    float* sYt = sm + OFF_YT;

    for (int iv = 0; iv < TT - 1; ++iv) {
        float t0v = sm[OFF_TS + iv];
        float h   = 0.5f * (sm[OFF_TS + iv + 1] - t0v);
        for (int sub = 0; sub < 2; ++sub) {
            float tc = t0v + sub * h;
            for (int s = 0; s < 6; ++s) {
                const float* aIn = (s == 0) ? sY : sYt;
                vf_eval(sm, s, h, tc + h * c_C6[s], aIn, tid);
            }
            // y updated inside s==5 epilogue of vf_eval
        }
        float* dst = out + (size_t)(iv + 1) * BB * DD + (size_t)r0 * DD;
        for (int i = tid; i < MT * DD; i += NTH) {
            int m = i >> 6, d = i & 63;
            dst[i] = sY[d * HP + m];
        }
    }
}

extern "C" void kernel_launch(void* const* d_in, const int* in_sizes, int n_in,
                              void* d_out, int out_size) {
    if (n_in < 8) return;
    const float* ts = (const float*)d_in[0];
    const float* y0 = (const float*)d_in[1];
    const float* W0 = (const float*)d_in[2];
    const float* b0 = (const float*)d_in[3];
    const float* W1 = (const float*)d_in[4];
    const float* b1 = (const float*)d_in[5];
    const float* W2 = (const float*)d_in[6];
    const float* b2 = (const float*)d_in[7];
    float* out = (float*)d_out;

    cudaFuncSetAttribute(ode_kernel, cudaFuncAttributeMaxDynamicSharedMemorySize, SMEM_BYTES);

    prep_kernel<<<256, 256>>>(W1, W2, y0, out);
    ode_kernel<<<NCTA, NTH, SMEM_BYTES>>>(ts, y0, W0, b0, b1, b2, out);
}